// round 17
// baseline (speedup 1.0000x reference)
#include <cuda_runtime.h>
#include <cuda_bf16.h>
#include <cstdint>

#define T_STEPS 4096
#define IDIM    512
#define HDIM    2048
#define ODIM    512
#define G4H     (4 * HDIM)   // 8192

#define NCTA 148
#define JPC  14              // 148*14 = 2072 >= 2048
#define RPC  56              // rows of W_hh per CTA
#define TPB  512             // 16 warps; warp w owns k-range [w*128, w*128+128)

// A tile geometry: 48 rows in smem (3 m16 tiles), 8 rows (48..55) as register frags
#define NSMEM_ROWS 48
#define A_STRIDE_B 4112      // 2048*2 + 16 pad: ldmatrix conflict-free (row shift = 4 banks)

// smem offsets (bytes)
#define OFF_A    0
#define OFF_HHI  (NSMEM_ROWS * A_STRIDE_B)            // 197,376
#define OFF_HLO  (OFF_HHI + HDIM * 2)                 // +4096
#define OFF_ZSM  (OFF_HLO + HDIM * 2)                 // +4096  (16 warps x 64 rows f32)
#define OFF_Z2   (OFF_ZSM + 16 * 64 * 4)              // +4096  (56 rows x 4 quarters f32)
#define SMEM_TOTAL (OFF_Z2 + RPC * 4 * 4)             // 210,560 B

// -------- persistent device state --------
__device__ __align__(16) float g_xz[(size_t)T_STEPS * G4H];
__device__ __align__(16) float g_h[2][HDIM];
__device__ unsigned int g_bar;

// ---------------------------------------------------------------------------
// Kernel 1: xz = X @ W_ih^T + (b_ih + b_hh)
// ---------------------------------------------------------------------------
__global__ __launch_bounds__(256) void xz_gemm(const float* __restrict__ A,
                                               const float* __restrict__ W,
                                               const float* __restrict__ b1,
                                               const float* __restrict__ b2) {
    if (blockIdx.x == 0 && blockIdx.y == 0 && threadIdx.x == 0) g_bar = 0u;

    __shared__ float a_sm[8][128];
    __shared__ float b_sm[8][128];

    const int tid = threadIdx.x;
    const int m0 = blockIdx.y * 128;
    const int n0 = blockIdx.x * 128;

    const int lr = tid >> 1;
    const int lk = (tid & 1) * 4;
    const float* Ap = A + (size_t)(m0 + lr) * IDIM + lk;
    const float* Wp = W + (size_t)(n0 + lr) * IDIM + lk;

    const int tx = tid & 15;
    const int ty = tid >> 4;

    float acc[8][8];
#pragma unroll
    for (int i = 0; i < 8; i++)
#pragma unroll
        for (int j = 0; j < 8; j++) acc[i][j] = 0.f;

    for (int k0 = 0; k0 < IDIM; k0 += 8) {
        float4 av = *(const float4*)(Ap + k0);
        float4 wv = *(const float4*)(Wp + k0);
        __syncthreads();
        a_sm[lk + 0][lr] = av.x; a_sm[lk + 1][lr] = av.y;
        a_sm[lk + 2][lr] = av.z; a_sm[lk + 3][lr] = av.w;
        b_sm[lk + 0][lr] = wv.x; b_sm[lk + 1][lr] = wv.y;
        b_sm[lk + 2][lr] = wv.z; b_sm[lk + 3][lr] = wv.w;
        __syncthreads();
#pragma unroll
        for (int kk = 0; kk < 8; kk++) {
            float ar[8], br[8];
            *(float4*)&ar[0] = *(const float4*)&a_sm[kk][ty * 8];
            *(float4*)&ar[4] = *(const float4*)&a_sm[kk][ty * 8 + 4];
            *(float4*)&br[0] = *(const float4*)&b_sm[kk][tx * 8];
            *(float4*)&br[4] = *(const float4*)&b_sm[kk][tx * 8 + 4];
#pragma unroll
            for (int i = 0; i < 8; i++)
#pragma unroll
                for (int j = 0; j < 8; j++) acc[i][j] += ar[i] * br[j];
        }
    }

    float bias[8];
#pragma unroll
    for (int j = 0; j < 8; j++) {
        int n = n0 + tx * 8 + j;
        bias[j] = b1[n] + b2[n];
    }
#pragma unroll
    for (int i = 0; i < 8; i++) {
        int m = m0 + ty * 8 + i;
        float* Crow = g_xz + (size_t)m * G4H + n0 + tx * 8;
        float4 o0 = make_float4(acc[i][0] + bias[0], acc[i][1] + bias[1],
                                acc[i][2] + bias[2], acc[i][3] + bias[3]);
        float4 o1 = make_float4(acc[i][4] + bias[4], acc[i][5] + bias[5],
                                acc[i][6] + bias[6], acc[i][7] + bias[7]);
        *(float4*)(Crow + 0) = o0;
        *(float4*)(Crow + 4) = o1;
    }
}

__global__ void prof_pad() {}

// ---------------------------------------------------------------------------
// mma / ldmatrix helpers
// ---------------------------------------------------------------------------
__device__ __forceinline__ void mma16816(float& c0, float& c1, float& c2, float& c3,
                                         unsigned a0, unsigned a1, unsigned a2, unsigned a3,
                                         unsigned b0, unsigned b1) {
    asm("mma.sync.aligned.m16n8k16.row.col.f32.bf16.bf16.f32 "
        "{%0,%1,%2,%3}, {%4,%5,%6,%7}, {%8,%9}, {%0,%1,%2,%3};"
        : "+f"(c0), "+f"(c1), "+f"(c2), "+f"(c3)
        : "r"(a0), "r"(a1), "r"(a2), "r"(a3), "r"(b0), "r"(b1));
}
__device__ __forceinline__ void ldsm4(unsigned& r0, unsigned& r1, unsigned& r2, unsigned& r3,
                                      unsigned addr) {
    asm volatile("ldmatrix.sync.aligned.m8n8.x4.shared.b16 {%0,%1,%2,%3}, [%4];"
                 : "=r"(r0), "=r"(r1), "=r"(r2), "=r"(r3) : "r"(addr));
}
__device__ __forceinline__ unsigned smem_u32(const void* p) {
    unsigned a;
    asm("{.reg .u64 t; cvta.to.shared.u64 t, %1; cvt.u32.u64 %0, t;}" : "=r"(a) : "l"(p));
    return a;
}
__device__ __forceinline__ float sigmoidf_fast(float x) { return 1.f / (1.f + __expf(-x)); }
__device__ __forceinline__ float tanh_fast(float x) {
    float ax = fminf(fmaxf(x, -15.f), 15.f);
    float e = __expf(2.f * ax);
    return (e - 1.f) / (e + 1.f);
}
__device__ __forceinline__ unsigned pack_bf2(float lo, float hi) {
    __nv_bfloat162 b = __floats2bfloat162_rn(lo, hi);
    return *(unsigned*)&b;
}

extern __shared__ __align__(16) unsigned char smem_dyn[];

// ---------------------------------------------------------------------------
// Kernel 2: persistent LSTM recurrence — tensor-core matvec.
//  z[56] = W_hh_bf16 @ (h_hi + h_lo), 4 m16 tiles x 128 k16 chunks, N replicated.
// ---------------------------------------------------------------------------
__global__ __launch_bounds__(TPB, 1) void lstm_rec(const float* __restrict__ Whh) {
    unsigned char* smem = smem_dyn;
    __nv_bfloat16* hhi = (__nv_bfloat16*)(smem + OFF_HHI);
    __nv_bfloat16* hlo = (__nv_bfloat16*)(smem + OFF_HLO);
    float* z_sm = (float*)(smem + OFF_ZSM);   // [16][64]
    float* z2   = (float*)(smem + OFF_Z2);    // [56][4]

    const int b = blockIdx.x;
    const int tid = threadIdx.x;
    const int warp = tid >> 5;
    const int lane = tid & 31;
    const int tig  = lane & 3;        // thread-in-group (mma col pair / B k pair)
    const int grp  = lane >> 2;       // mma row group 0..7
    const int jbase = b * JPC;

    // ---- prologue A: rows 0..47 of W (this CTA's slice) -> smem bf16, padded stride ----
    for (int r = 0; r < NSMEM_ROWS; r++) {
        int gate = r / JPC;
        int jl = r - gate * JPC;
        int j = jbase + jl;
        unsigned char* dst = smem + OFF_A + (size_t)r * A_STRIDE_B;
        if (j < HDIM) {
            const float4* src = (const float4*)(Whh + (size_t)(gate * HDIM + j) * HDIM);
            for (int k = tid; k < HDIM / 4; k += TPB) {
                float4 v = src[k];
                *(__nv_bfloat162*)(dst + k * 8)     = __floats2bfloat162_rn(v.x, v.y);
                *(__nv_bfloat162*)(dst + k * 8 + 4) = __floats2bfloat162_rn(v.z, v.w);
            }
        } else {
            for (int k = tid; k < HDIM / 2; k += TPB)
                *(__nv_bfloat162*)(dst + k * 4) = __floats2bfloat162_rn(0.f, 0.f);
        }
    }

    // ---- prologue B: tile-3 register A-fragments (rows 48..55, dup as rows 8-15) ----
    // thread holds a0,a2 for each of its warp's 8 k-chunks; a1=a0, a3=a2 at mma time.
    unsigned wfrag[16];
    {
        int r = 48 + grp;                 // global row 48..55 -> gate 3, jl = 6+grp
        int j = jbase + (r - 42);
        const int kb = warp * 128;
        if (j < HDIM) {
            const float* rowp = Whh + (size_t)(3 * HDIM + j) * HDIM;
#pragma unroll
            for (int kc = 0; kc < 8; kc++) {
                int k0 = kb + kc * 16 + 2 * tig;
                wfrag[2 * kc]     = pack_bf2(rowp[k0],     rowp[k0 + 1]);
                wfrag[2 * kc + 1] = pack_bf2(rowp[k0 + 8], rowp[k0 + 9]);
            }
        } else {
#pragma unroll
            for (int k = 0; k < 16; k++) wfrag[k] = 0u;
        }
    }

    // zero initial hidden state slice
    if (tid < JPC && jbase + tid < HDIM) g_h[0][jbase + tid] = 0.f;

    const bool gate_lane = (tid < JPC) && (jbase + tid < HDIM);
    float c_state = 0.f;
    unsigned int phase = 0;

    // prologue grid barrier
    phase += NCTA;
    __syncthreads();
    if (tid == 0) {
        asm volatile("red.release.gpu.global.add.u32 [%0], 1;" :: "l"(&g_bar) : "memory");
        unsigned int v;
        do {
            asm volatile("ld.acquire.gpu.u32 %0, [%1];" : "=r"(v) : "l"(&g_bar));
            if (v >= phase) break;
            __nanosleep(32);
        } while (true);
    }
    __syncthreads();

    // per-lane ldmatrix row-address component (lanes 0-15: rows 0-15 col-byte 0;
    // lanes 16-31: rows 0-15 col-byte 16) — canonical A m16k16 row-major pattern
    const unsigned a_base = smem_u32(smem + OFF_A) + (lane & 15) * A_STRIDE_B + (lane >> 4) * 16;
    const int kb = warp * 128;

    for (int t = 0; t < T_STEPS; t++) {
        // gate lanes prefetch xz (hidden under matvec)
        float xz0 = 0.f, xz1 = 0.f, xz2 = 0.f, xz3 = 0.f;
        if (gate_lane) {
            const float* xp = g_xz + (size_t)t * G4H + jbase + tid;
            xz0 = __ldcg(xp);
            xz1 = __ldcg(xp + HDIM);
            xz2 = __ldcg(xp + 2 * HDIM);
            xz3 = __ldcg(xp + 3 * HDIM);
        }

        // ---- stage h: fp32 -> bf16 hi + bf16 lo residual ----
        {
            float4 v = __ldcg(((const float4*)g_h[t & 1]) + tid);
            __nv_bfloat16 bx = __float2bfloat16_rn(v.x);
            __nv_bfloat16 by = __float2bfloat16_rn(v.y);
            __nv_bfloat16 bz = __float2bfloat16_rn(v.z);
            __nv_bfloat16 bw = __float2bfloat16_rn(v.w);
            float lx = v.x - __bfloat162float(bx);
            float ly = v.y - __bfloat162float(by);
            float lz = v.z - __bfloat162float(bz);
            float lw = v.w - __bfloat162float(bw);
            uint2 hi2, lo2;
            hi2.x = (unsigned)*(unsigned short*)&bx | ((unsigned)*(unsigned short*)&by << 16);
            hi2.y = (unsigned)*(unsigned short*)&bz | ((unsigned)*(unsigned short*)&bw << 16);
            lo2.x = pack_bf2(lx, ly);
            lo2.y = pack_bf2(lz, lw);
            *(uint2*)&hhi[4 * tid] = hi2;
            *(uint2*)&hlo[4 * tid] = lo2;
        }
        __syncthreads();

        // ---- tensor-core matvec: 4 M-tiles, this warp's 8 k16 chunks ----
        float C[4][4];
#pragma unroll
        for (int m = 0; m < 4; m++)
#pragma unroll
            for (int i = 0; i < 4; i++) C[m][i] = 0.f;

#pragma unroll
        for (int kc = 0; kc < 8; kc++) {
            const int kcol = kb + kc * 16;
            unsigned bh0 = *(const unsigned*)&hhi[kcol + 2 * tig];
            unsigned bh1 = *(const unsigned*)&hhi[kcol + 2 * tig + 8];
            unsigned bl0 = *(const unsigned*)&hlo[kcol + 2 * tig];
            unsigned bl1 = *(const unsigned*)&hlo[kcol + 2 * tig + 8];
#pragma unroll
            for (int mt = 0; mt < 3; mt++) {
                unsigned a0, a1, a2, a3;
                ldsm4(a0, a1, a2, a3, a_base + mt * (16 * A_STRIDE_B) + kcol * 2);
                mma16816(C[mt][0], C[mt][1], C[mt][2], C[mt][3], a0, a1, a2, a3, bh0, bh1);
                mma16816(C[mt][0], C[mt][1], C[mt][2], C[mt][3], a0, a1, a2, a3, bl0, bl1);
            }
            {   // tile 3 from registers (rows 8-15 duplicate 0-7)
                unsigned a0 = wfrag[2 * kc], a2 = wfrag[2 * kc + 1];
                mma16816(C[3][0], C[3][1], C[3][2], C[3][3], a0, a0, a2, a2, bh0, bh1);
                mma16816(C[3][0], C[3][1], C[3][2], C[3][3], a0, a0, a2, a2, bl0, bl1);
            }
        }

        // ---- store per-warp row partials (all B cols equal -> c0 = z[row]) ----
        if (tig == 0) {
            float* zw = z_sm + warp * 64;
            zw[grp]      = C[0][0];
            zw[grp + 8]  = C[0][2];
            zw[16 + grp]     = C[1][0];
            zw[16 + grp + 8] = C[1][2];
            zw[32 + grp]     = C[2][0];
            zw[32 + grp + 8] = C[2][2];
            zw[48 + grp]     = C[3][0];   // rows 48..55 (c2 is the duplicate, discard)
        }
        __syncthreads();

        // ---- reduce 16 warp-partials per row: phase 1 (4 quarters) ----
        if (tid < RPC * 4) {
            int row = tid >> 2, q = tid & 3;
            const float* zp = z_sm + (q * 4) * 64 + row;
            z2[tid] = (zp[0] + zp[64]) + (zp[128] + zp[192]);
        }
        __syncthreads();

        // ---- gates ----
        if (gate_lane) {
            int j = jbase + tid;
            const float* z2p = z2;
            float zi = xz0 + ((z2p[4 * tid]            + z2p[4 * tid + 1])            + (z2p[4 * tid + 2]            + z2p[4 * tid + 3]));
            float zf = xz1 + ((z2p[4 * (JPC + tid)]     + z2p[4 * (JPC + tid) + 1])    + (z2p[4 * (JPC + tid) + 2]    + z2p[4 * (JPC + tid) + 3]));
            float zg = xz2 + ((z2p[4 * (2 * JPC + tid)] + z2p[4 * (2 * JPC + tid) + 1]) + (z2p[4 * (2 * JPC + tid) + 2] + z2p[4 * (2 * JPC + tid) + 3]));
            float zo = xz3 + ((z2p[4 * (3 * JPC + tid)] + z2p[4 * (3 * JPC + tid) + 1]) + (z2p[4 * (3 * JPC + tid) + 2] + z2p[4 * (3 * JPC + tid) + 3]));
            float ig = sigmoidf_fast(zi);
            float fg = sigmoidf_fast(zf);
            float gg = tanh_fast(zg);
            float og = sigmoidf_fast(zo);
            c_state = fg * c_state + ig * gg;
            g_h[(t + 1) & 1][j] = og * tanh_fast(c_state);
        }
        __syncwarp();   // warp0: h-stores ordered before tid0's release

        // grid barrier
        phase += NCTA;
        if (tid == 0) {
            asm volatile("red.release.gpu.global.add.u32 [%0], 1;" :: "l"(&g_bar) : "memory");
            unsigned int v;
            do {
                asm volatile("ld.acquire.gpu.u32 %0, [%1];" : "=r"(v) : "l"(&g_bar));
                if (v >= phase) break;
                __nanosleep(32);
            } while (true);
        }
        __syncthreads();
    }
}

// ---------------------------------------------------------------------------
// Kernel 3: out = W_lin @ h_T + b_lin   (h_T in g_h[0])
// ---------------------------------------------------------------------------
__global__ __launch_bounds__(256) void final_linear(const float* __restrict__ Wlin,
                                                    const float* __restrict__ blin,
                                                    float* __restrict__ out) {
    const float* h = g_h[0];
    const int o = blockIdx.x;
    const int tid = threadIdx.x;
    const float* wr = Wlin + (size_t)o * HDIM;

    float s = 0.f;
    for (int j = tid; j < HDIM; j += 256) s += wr[j] * h[j];

    __shared__ float red[8];
#pragma unroll
    for (int off = 16; off; off >>= 1) s += __shfl_xor_sync(0xffffffffu, s, off);
    if ((tid & 31) == 0) red[tid >> 5] = s;
    __syncthreads();
    if (tid < 32) {
        float v = (tid < 8) ? red[tid] : 0.f;
#pragma unroll
        for (int off = 16; off; off >>= 1) v += __shfl_xor_sync(0xffffffffu, v, off);
        if (tid == 0) out[o] = v + blin[o];
    }
}

// ---------------------------------------------------------------------------
extern "C" void kernel_launch(void* const* d_in, const int* in_sizes, int n_in,
                              void* d_out, int out_size) {
    const float* x    = (const float*)d_in[0];
    const float* Wih  = (const float*)d_in[1];
    const float* Whh  = (const float*)d_in[2];
    const float* bih  = (const float*)d_in[3];
    const float* bhh  = (const float*)d_in[4];
    const float* Wlin = (const float*)d_in[5];
    const float* blin = (const float*)d_in[6];
    float* out = (float*)d_out;

    cudaFuncSetAttribute(lstm_rec, cudaFuncAttributeMaxDynamicSharedMemorySize, SMEM_TOTAL);

    dim3 gg(G4H / 128, T_STEPS / 128);
    xz_gemm<<<gg, 256>>>(x, Wih, bih, bhh);        // also resets g_bar
    prof_pad<<<1, 1>>>();
    prof_pad<<<1, 1>>>();
    prof_pad<<<1, 1>>>();
    lstm_rec<<<NCTA, TPB, SMEM_TOTAL>>>(Whh);
    final_linear<<<ODIM, 256>>>(Wlin, blin, out);
}